// round 2
// baseline (speedup 1.0000x reference)
#include <cuda_runtime.h>
#include <cuda_bf16.h>
#include <math.h>

// Problem constants
#define BATCH 4
#define SEQ   2048
#define EMB   1024
#define MTOT  (BATCH * SEQ)   // 8192

// Scratch (static device globals: allowed; no allocation at runtime)
__device__ float g_Q[(size_t)MTOT * EMB];
__device__ float g_K[(size_t)MTOT * EMB];
__device__ float g_V[(size_t)MTOT * EMB];
__device__ float g_S[(size_t)BATCH * SEQ * SEQ];

// ---------------------------------------------------------------------------
// Generic 128x128x16 SGEMM, 256 threads, 8x8 register tile per thread.
//   A: [M,K] row-major (lda = K stride)
//   TRANSB=true : B is [N,K] row-major, C = A * B^T   (NT)
//   TRANSB=false: B is [K,N] row-major, C = A * B     (NN)
// mode 0: C += bias[n]          (QKV projection)
// mode 1: C *= 1/32, skip blocks with n0 > m0 (causal scores)
// mode 2: k-loop bounded at m0+BM (causal PV)
// blockIdx.z = batch index (strides sA/sB/sC in elements)
// ---------------------------------------------------------------------------
template <bool TRANSB>
__global__ void __launch_bounds__(256, 2)
sgemm_kernel(const float* __restrict__ A, const float* __restrict__ B,
             float* __restrict__ C, const float* __restrict__ bias,
             int M, int N, int K, int lda, int ldb, int ldc, int mode,
             size_t sA, size_t sB, size_t sC)
{
    constexpr int BM = 128, BN = 128, BK = 16;
    __shared__ __align__(16) float As[BK][BM + 4];
    __shared__ __align__(16) float Bs[BK][BN + 4];

    const int bz = blockIdx.z;
    A += (size_t)bz * sA;
    B += (size_t)bz * sB;
    C += (size_t)bz * sC;

    const int m0 = blockIdx.y * BM;
    const int n0 = blockIdx.x * BN;
    if (mode == 1 && n0 > m0) return;           // strictly-upper causal block: never read

    int kmax = K;
    if (mode == 2) { int kb = m0 + BM; kmax = kb < K ? kb : K; }

    const int tid = threadIdx.x;
    const int tx  = tid & 15;                   // 16 cols of threads
    const int ty  = tid >> 4;                   // 16 rows of threads
    const int tmB = ty * 8;
    const int tnB = tx * 8;

    float acc[8][8];
#pragma unroll
    for (int i = 0; i < 8; ++i)
#pragma unroll
        for (int j = 0; j < 8; ++j) acc[i][j] = 0.0f;

    for (int k0 = 0; k0 < kmax; k0 += BK) {
        // ---- load A tile [BM x BK], store transposed As[k][m] ----
#pragma unroll
        for (int r = 0; r < 2; ++r) {
            int v   = tid + r * 256;            // 512 float4 total
            int row = v >> 2;
            int kq  = (v & 3) << 2;
            float4 t = *(const float4*)&A[(size_t)(m0 + row) * lda + k0 + kq];
            As[kq + 0][row] = t.x;
            As[kq + 1][row] = t.y;
            As[kq + 2][row] = t.z;
            As[kq + 3][row] = t.w;
        }
        // ---- load B tile ----
#pragma unroll
        for (int r = 0; r < 2; ++r) {
            int v = tid + r * 256;
            if (TRANSB) {                       // B [N,K]: transpose into Bs[k][n]
                int row = v >> 2;
                int kq  = (v & 3) << 2;
                float4 t = *(const float4*)&B[(size_t)(n0 + row) * ldb + k0 + kq];
                Bs[kq + 0][row] = t.x;
                Bs[kq + 1][row] = t.y;
                Bs[kq + 2][row] = t.z;
                Bs[kq + 3][row] = t.w;
            } else {                            // B [K,N]: direct Bs[k][n]
                int krow = v >> 5;
                int nq   = (v & 31) << 2;
                float4 t = *(const float4*)&B[(size_t)(k0 + krow) * ldb + n0 + nq];
                *(float4*)&Bs[krow][nq] = t;
            }
        }
        __syncthreads();

#pragma unroll
        for (int k = 0; k < BK; ++k) {
            float a[8], b[8];
            *(float4*)&a[0] = *(const float4*)&As[k][tmB];
            *(float4*)&a[4] = *(const float4*)&As[k][tmB + 4];
            *(float4*)&b[0] = *(const float4*)&Bs[k][tnB];
            *(float4*)&b[4] = *(const float4*)&Bs[k][tnB + 4];
#pragma unroll
            for (int i = 0; i < 8; ++i)
#pragma unroll
                for (int j = 0; j < 8; ++j)
                    acc[i][j] = fmaf(a[i], b[j], acc[i][j]);
        }
        __syncthreads();
    }

    // ---- epilogue ----
    float bv[8];
    if (mode == 0) {
#pragma unroll
        for (int j = 0; j < 8; ++j) bv[j] = bias[n0 + tnB + j];
    }
    const float scale = (mode == 1) ? 0.03125f : 1.0f;

#pragma unroll
    for (int i = 0; i < 8; ++i) {
        size_t crow = (size_t)(m0 + tmB + i) * ldc + n0 + tnB;
#pragma unroll
        for (int j = 0; j < 8; j += 4) {
            float4 t;
            t.x = acc[i][j + 0] * scale;
            t.y = acc[i][j + 1] * scale;
            t.z = acc[i][j + 2] * scale;
            t.w = acc[i][j + 3] * scale;
            if (mode == 0) {
                t.x += bv[j + 0]; t.y += bv[j + 1];
                t.z += bv[j + 2]; t.w += bv[j + 3];
            }
            *(float4*)&C[crow + j] = t;
        }
    }
}

// ---------------------------------------------------------------------------
// Causal row softmax, in place on g_S. One block (256 threads) per row.
// Row q only attends to j <= q. We process j in [0, kend) where kend is the
// 128-aligned end of the diagonal block; masked entries get exact 0 written
// so the PV GEMM can use a block-granular k bound with no per-element mask.
// ---------------------------------------------------------------------------
__global__ void __launch_bounds__(256)
softmax_kernel(float* __restrict__ Sc)
{
    const int row = blockIdx.x;                 // 0 .. BATCH*SEQ-1
    const int q   = row & (SEQ - 1);
    float* r = Sc + (size_t)row * SEQ;
    const int kend = ((q >> 7) + 1) << 7;       // multiple of 128, <= SEQ
    const int tid = threadIdx.x;

    float vals[8];
    float mx = -INFINITY;
    {
        int it = 0;
        for (int j = tid; j < kend; j += 256, ++it) {
            float v = (j <= q) ? r[j] : -INFINITY;
            vals[it] = v;
            mx = fmaxf(mx, v);
        }
    }

    __shared__ float red[8];
#pragma unroll
    for (int o = 16; o > 0; o >>= 1) mx = fmaxf(mx, __shfl_xor_sync(0xffffffffu, mx, o));
    if ((tid & 31) == 0) red[tid >> 5] = mx;
    __syncthreads();
    if (tid == 0) {
        float m = red[0];
#pragma unroll
        for (int i = 1; i < 8; ++i) m = fmaxf(m, red[i]);
        red[0] = m;
    }
    __syncthreads();
    mx = red[0];
    __syncthreads();                            // before red[] is reused

    float sum = 0.0f;
    {
        int it = 0;
        for (int j = tid; j < kend; j += 256, ++it) {
            float e = __expf(vals[it] - mx);    // masked -> exp(-inf) = 0
            vals[it] = e;
            sum += e;
        }
    }
#pragma unroll
    for (int o = 16; o > 0; o >>= 1) sum += __shfl_xor_sync(0xffffffffu, sum, o);
    if ((tid & 31) == 0) red[tid >> 5] = sum;
    __syncthreads();
    if (tid == 0) {
        float s = red[0];
#pragma unroll
        for (int i = 1; i < 8; ++i) s += red[i];
        red[0] = s;
    }
    __syncthreads();
    const float inv = 1.0f / red[0];

    {
        int it = 0;
        for (int j = tid; j < kend; j += 256, ++it) r[j] = vals[it] * inv;
    }
}

// ---------------------------------------------------------------------------
// Launch. Inputs (metadata order): x, Wq, bq, Wk, bk, Wv, bv, mask.
// mask is the known causal tril -> ignored, causality is hardcoded.
// ---------------------------------------------------------------------------
extern "C" void kernel_launch(void* const* d_in, const int* in_sizes, int n_in,
                              void* d_out, int out_size)
{
    const float* x  = (const float*)d_in[0];
    const float* Wq = (const float*)d_in[1];
    const float* bq = (const float*)d_in[2];
    const float* Wk = (const float*)d_in[3];
    const float* bk = (const float*)d_in[4];
    const float* Wv = (const float*)d_in[5];
    const float* bv = (const float*)d_in[6];
    float* out = (float*)d_out;

    float *Q, *Kp, *Vp, *Sc;
    cudaGetSymbolAddress((void**)&Q,  g_Q);
    cudaGetSymbolAddress((void**)&Kp, g_K);
    cudaGetSymbolAddress((void**)&Vp, g_V);
    cudaGetSymbolAddress((void**)&Sc, g_S);

    dim3 blk(256);

    // 1) QKV projections: [8192,1024] x [1024,1024]^T + bias   (NT, mode 0)
    dim3 gQKV(EMB / 128, MTOT / 128, 1);
    sgemm_kernel<true><<<gQKV, blk>>>(x, Wq, Q,  bq, MTOT, EMB, EMB, EMB, EMB, EMB, 0, 0, 0, 0);
    sgemm_kernel<true><<<gQKV, blk>>>(x, Wk, Kp, bk, MTOT, EMB, EMB, EMB, EMB, EMB, 0, 0, 0, 0);
    sgemm_kernel<true><<<gQKV, blk>>>(x, Wv, Vp, bv, MTOT, EMB, EMB, EMB, EMB, EMB, 0, 0, 0, 0);

    // 2) scores = Q K^T / sqrt(E), causal block skip   (NT, mode 1, batched)
    dim3 gS(SEQ / 128, SEQ / 128, BATCH);
    sgemm_kernel<true><<<gS, blk>>>(Q, Kp, Sc, nullptr, SEQ, SEQ, EMB,
                                    EMB, EMB, SEQ, 1,
                                    (size_t)SEQ * EMB, (size_t)SEQ * EMB, (size_t)SEQ * SEQ);

    // 3) causal softmax in place
    softmax_kernel<<<BATCH * SEQ, blk>>>(Sc);

    // 4) out = P V, k bounded by causal structure   (NN, mode 2, batched)
    dim3 gPV(EMB / 128, SEQ / 128, BATCH);
    sgemm_kernel<false><<<gPV, blk>>>(Sc, Vp, out, nullptr, SEQ, EMB, SEQ,
                                      SEQ, EMB, EMB, 2,
                                      (size_t)SEQ * SEQ, (size_t)SEQ * EMB, (size_t)SEQ * EMB);
}